// round 1
// baseline (speedup 1.0000x reference)
#include <cuda_runtime.h>
#include <cuda_bf16.h>
#include <math.h>
#include <stddef.h>

// Problem constants
#define Bq   4
#define Sq   2048
#define Hq   16
#define DKq  64
#define DMq  1024
// Derived
#define OUT_ELEMS   ((size_t)Bq * Sq * DMq)                 // 8,388,608
#define ATTN_ELEMS  ((size_t)Bq * Hq * Sq * (size_t)Sq)     // 268,435,456

// ---------------- scratch (allocation-free: __device__ globals) ----------------
__device__ float g_q  [Bq * Sq * DMq];     // 32 MB  [B,S,H*DK]
__device__ float g_k  [Bq * Sq * DMq];     // 32 MB
__device__ float g_v  [Bq * Sq * DMq];     // 32 MB
__device__ float g_ctx[Bq * Sq * DMq];     // 32 MB
__device__ float g_attn_scratch[ATTN_ELEMS]; // 1 GB fallback if harness only wants `out`

// =====================================================================
// GEMM: C[M,N] = A[M,K] * W[K,N]  (+ optional residual), row-major all.
// BM=128, BN=128, BK=16, 256 threads, 8x8 per-thread micro-tile.
// M,N,K multiples of tile sizes (8192/1024/1024 here).
// =====================================================================
template<bool RES>
__global__ __launch_bounds__(256)
void gemm_xw_kernel(const float* __restrict__ A, const float* __restrict__ W,
                    const float* __restrict__ res, float* __restrict__ C,
                    int M, int N, int K)
{
    __shared__ float As[16][132];   // transposed: As[k][m], padded
    __shared__ float Bs[16][128];

    const int tid = threadIdx.x;
    const int bm  = blockIdx.y * 128;
    const int bn  = blockIdx.x * 128;
    const int tx  = tid & 15;        // 0..15 -> n
    const int ty  = tid >> 4;        // 0..15 -> m

    float acc[8][8];
    #pragma unroll
    for (int i = 0; i < 8; i++)
        #pragma unroll
        for (int j = 0; j < 8; j++) acc[i][j] = 0.f;

    for (int k0 = 0; k0 < K; k0 += 16) {
        // Load A tile 128x16 as float4 (512 float4s, 2 per thread), store transposed
        #pragma unroll
        for (int i = 0; i < 2; i++) {
            int f4 = tid + i * 256;
            int m  = f4 >> 2;
            int kq = (f4 & 3) * 4;
            float4 v = *reinterpret_cast<const float4*>(&A[(size_t)(bm + m) * K + k0 + kq]);
            As[kq + 0][m] = v.x; As[kq + 1][m] = v.y;
            As[kq + 2][m] = v.z; As[kq + 3][m] = v.w;
        }
        // Load B tile 16x128 as float4 (512 float4s, 2 per thread)
        #pragma unroll
        for (int i = 0; i < 2; i++) {
            int f4 = tid + i * 256;
            int kk = f4 >> 5;
            int nq = (f4 & 31) * 4;
            float4 v = *reinterpret_cast<const float4*>(&W[(size_t)(k0 + kk) * N + bn + nq]);
            *reinterpret_cast<float4*>(&Bs[kk][nq]) = v;
        }
        __syncthreads();

        #pragma unroll
        for (int kk = 0; kk < 16; kk++) {
            float ra[8], rb[8];
            #pragma unroll
            for (int i = 0; i < 8; i++) ra[i] = As[kk][ty * 8 + i];
            #pragma unroll
            for (int j = 0; j < 8; j++) rb[j] = Bs[kk][tx * 8 + j];
            #pragma unroll
            for (int i = 0; i < 8; i++)
                #pragma unroll
                for (int j = 0; j < 8; j++)
                    acc[i][j] = fmaf(ra[i], rb[j], acc[i][j]);
        }
        __syncthreads();
    }

    #pragma unroll
    for (int i = 0; i < 8; i++) {
        const int m = bm + ty * 8 + i;
        const int n = bn + tx * 8;
        float* cp = &C[(size_t)m * N + n];
        if (RES) {
            const float* rp = &res[(size_t)m * N + n];
            float4 r0 = *reinterpret_cast<const float4*>(rp);
            float4 r1 = *reinterpret_cast<const float4*>(rp + 4);
            float4 o0 = make_float4(acc[i][0] + r0.x, acc[i][1] + r0.y,
                                    acc[i][2] + r0.z, acc[i][3] + r0.w);
            float4 o1 = make_float4(acc[i][4] + r1.x, acc[i][5] + r1.y,
                                    acc[i][6] + r1.z, acc[i][7] + r1.w);
            *reinterpret_cast<float4*>(cp)     = o0;
            *reinterpret_cast<float4*>(cp + 4) = o1;
        } else {
            float4 o0 = make_float4(acc[i][0], acc[i][1], acc[i][2], acc[i][3]);
            float4 o1 = make_float4(acc[i][4], acc[i][5], acc[i][6], acc[i][7]);
            *reinterpret_cast<float4*>(cp)     = o0;
            *reinterpret_cast<float4*>(cp + 4) = o1;
        }
    }
}

// =====================================================================
// Scores: attn[bh, q, k] = (1/8) * sum_d Q[b,q,h,d] * K[b,k,h,d]
// Q/K rows strided by DM=1024. Tile 128x128, d processed in 2 chunks of 32.
// grid: (ktile=16, qtile=16, bh=64)
// =====================================================================
__global__ __launch_bounds__(256)
void scores_kernel(const float* __restrict__ Q, const float* __restrict__ Kv,
                   float* __restrict__ attn)
{
    __shared__ float Qs[32][130];   // [d][s]
    __shared__ float Ks[32][130];

    const int bh = blockIdx.z;
    const int b  = bh >> 4;
    const int h  = bh & 15;
    const float* qb = Q  + (size_t)b * Sq * DMq + h * DKq;
    const float* kb = Kv + (size_t)b * Sq * DMq + h * DKq;
    const int q0 = blockIdx.y * 128;
    const int k0 = blockIdx.x * 128;

    const int tid = threadIdx.x;
    const int tx  = tid & 15;
    const int ty  = tid >> 4;

    float acc[8][8];
    #pragma unroll
    for (int i = 0; i < 8; i++)
        #pragma unroll
        for (int j = 0; j < 8; j++) acc[i][j] = 0.f;

    for (int d0 = 0; d0 < 64; d0 += 32) {
        // 128x32 per matrix = 1024 float4s, 4 per thread each
        #pragma unroll
        for (int i = 0; i < 4; i++) {
            int f4 = tid + i * 256;
            int s  = f4 >> 3;
            int dq = (f4 & 7) * 4;
            float4 vq = *reinterpret_cast<const float4*>(&qb[(size_t)(q0 + s) * DMq + d0 + dq]);
            float4 vk = *reinterpret_cast<const float4*>(&kb[(size_t)(k0 + s) * DMq + d0 + dq]);
            Qs[dq + 0][s] = vq.x; Qs[dq + 1][s] = vq.y; Qs[dq + 2][s] = vq.z; Qs[dq + 3][s] = vq.w;
            Ks[dq + 0][s] = vk.x; Ks[dq + 1][s] = vk.y; Ks[dq + 2][s] = vk.z; Ks[dq + 3][s] = vk.w;
        }
        __syncthreads();

        #pragma unroll
        for (int dd = 0; dd < 32; dd++) {
            float ra[8], rb[8];
            #pragma unroll
            for (int i = 0; i < 8; i++) ra[i] = Qs[dd][ty * 8 + i];
            #pragma unroll
            for (int j = 0; j < 8; j++) rb[j] = Ks[dd][tx * 8 + j];
            #pragma unroll
            for (int i = 0; i < 8; i++)
                #pragma unroll
                for (int j = 0; j < 8; j++)
                    acc[i][j] = fmaf(ra[i], rb[j], acc[i][j]);
        }
        __syncthreads();
    }

    const float sc = 0.125f;  // 1/sqrt(64)
    const size_t base = (size_t)bh * Sq * (size_t)Sq;
    #pragma unroll
    for (int i = 0; i < 8; i++) {
        size_t row = base + (size_t)(q0 + ty * 8 + i) * Sq + (k0 + tx * 8);
        float4 o0 = make_float4(acc[i][0]*sc, acc[i][1]*sc, acc[i][2]*sc, acc[i][3]*sc);
        float4 o1 = make_float4(acc[i][4]*sc, acc[i][5]*sc, acc[i][6]*sc, acc[i][7]*sc);
        *reinterpret_cast<float4*>(&attn[row])     = o0;
        *reinterpret_cast<float4*>(&attn[row + 4]) = o1;
    }
}

// =====================================================================
// Row softmax in place: 131072 rows of 2048, one block (256 thr) per row.
// =====================================================================
__global__ __launch_bounds__(256)
void softmax_kernel(float* __restrict__ attn)
{
    __shared__ float red[256];
    const size_t row = (size_t)blockIdx.x;
    float* p = attn + row * Sq;
    const int tid = threadIdx.x;

    float v[8];
    float mx = -INFINITY;
    #pragma unroll
    for (int i = 0; i < 8; i++) {
        v[i] = p[tid + i * 256];
        mx = fmaxf(mx, v[i]);
    }
    red[tid] = mx;
    __syncthreads();
    #pragma unroll
    for (int s = 128; s > 0; s >>= 1) {
        if (tid < s) red[tid] = fmaxf(red[tid], red[tid + s]);
        __syncthreads();
    }
    mx = red[0];
    __syncthreads();

    float sum = 0.f;
    #pragma unroll
    for (int i = 0; i < 8; i++) {
        v[i] = __expf(v[i] - mx);
        sum += v[i];
    }
    red[tid] = sum;
    __syncthreads();
    #pragma unroll
    for (int s = 128; s > 0; s >>= 1) {
        if (tid < s) red[tid] += red[tid + s];
        __syncthreads();
    }
    const float inv = 1.f / red[0];
    #pragma unroll
    for (int i = 0; i < 8; i++)
        p[tid + i * 256] = v[i] * inv;
}

// =====================================================================
// ctx[b,s,h,:] = attn[bh, s, :] @ V[b,:,h,:]
// Per (bh): [2048 x 2048] @ [2048 x 64]. BM=128, BN=64, BK=32.
// grid: (mtile=16, bh=64); 256 threads, 8x4 micro-tile.
// =====================================================================
__global__ __launch_bounds__(256)
void ctx_kernel(const float* __restrict__ attn, const float* __restrict__ V,
                float* __restrict__ ctx)
{
    __shared__ float As[128][33];
    __shared__ float Vs[32][64];

    const int bh = blockIdx.y;
    const int b  = bh >> 4;
    const int h  = bh & 15;
    const float* ab = attn + (size_t)bh * Sq * (size_t)Sq;
    const float* vb = V    + (size_t)b * Sq * DMq + h * DKq;
    const int m0 = blockIdx.x * 128;

    const int tid = threadIdx.x;
    const int tx  = tid & 15;   // n: tx*4
    const int ty  = tid >> 4;   // m: ty*8

    float acc[8][4];
    #pragma unroll
    for (int i = 0; i < 8; i++)
        #pragma unroll
        for (int j = 0; j < 4; j++) acc[i][j] = 0.f;

    for (int k0 = 0; k0 < Sq; k0 += 32) {
        // attn tile 128x32 = 1024 float4s, 4 per thread
        #pragma unroll
        for (int i = 0; i < 4; i++) {
            int f4 = tid + i * 256;
            int m  = f4 >> 3;
            int kq = (f4 & 7) * 4;
            float4 v = *reinterpret_cast<const float4*>(&ab[(size_t)(m0 + m) * Sq + k0 + kq]);
            As[m][kq + 0] = v.x; As[m][kq + 1] = v.y;
            As[m][kq + 2] = v.z; As[m][kq + 3] = v.w;
        }
        // V tile 32x64 = 512 float4s, 2 per thread
        #pragma unroll
        for (int i = 0; i < 2; i++) {
            int f4 = tid + i * 256;
            int kk = f4 >> 4;
            int nq = (f4 & 15) * 4;
            float4 v = *reinterpret_cast<const float4*>(&vb[(size_t)(k0 + kk) * DMq + nq]);
            *reinterpret_cast<float4*>(&Vs[kk][nq]) = v;
        }
        __syncthreads();

        #pragma unroll
        for (int kk = 0; kk < 32; kk++) {
            float ra[8], rb[4];
            #pragma unroll
            for (int i = 0; i < 8; i++) ra[i] = As[ty * 8 + i][kk];
            #pragma unroll
            for (int j = 0; j < 4; j++) rb[j] = Vs[kk][tx * 4 + j];
            #pragma unroll
            for (int i = 0; i < 8; i++)
                #pragma unroll
                for (int j = 0; j < 4; j++)
                    acc[i][j] = fmaf(ra[i], rb[j], acc[i][j]);
        }
        __syncthreads();
    }

    #pragma unroll
    for (int i = 0; i < 8; i++) {
        int s = m0 + ty * 8 + i;
        float4 o = make_float4(acc[i][0], acc[i][1], acc[i][2], acc[i][3]);
        *reinterpret_cast<float4*>(&ctx[(size_t)(b * Sq + s) * DMq + h * DKq + tx * 4]) = o;
    }
}

// =====================================================================
// LayerNorm in place: 8192 rows of 1024, one block (256 thr) per row.
// =====================================================================
__global__ __launch_bounds__(256)
void ln_kernel(float* __restrict__ out, const float* __restrict__ gamma,
               const float* __restrict__ beta)
{
    __shared__ float red[256];
    const size_t row = (size_t)blockIdx.x;
    float* p = out + row * DMq;
    const int tid = threadIdx.x;

    float v[4];
    float s = 0.f;
    #pragma unroll
    for (int i = 0; i < 4; i++) {
        v[i] = p[tid + i * 256];
        s += v[i];
    }
    red[tid] = s;
    __syncthreads();
    #pragma unroll
    for (int st = 128; st > 0; st >>= 1) {
        if (tid < st) red[tid] += red[tid + st];
        __syncthreads();
    }
    const float mu = red[0] * (1.f / DMq);
    __syncthreads();

    float s2 = 0.f;
    #pragma unroll
    for (int i = 0; i < 4; i++) {
        float d = v[i] - mu;
        s2 += d * d;
    }
    red[tid] = s2;
    __syncthreads();
    #pragma unroll
    for (int st = 128; st > 0; st >>= 1) {
        if (tid < st) red[tid] += red[tid + st];
        __syncthreads();
    }
    const float inv = rsqrtf(red[0] * (1.f / DMq) + 1e-6f);
    #pragma unroll
    for (int i = 0; i < 4; i++) {
        int c = tid + i * 256;
        p[c] = (v[i] - mu) * inv * gamma[c] + beta[c];
    }
}

// =====================================================================
extern "C" void kernel_launch(void* const* d_in, const int* in_sizes, int n_in,
                              void* d_out, int out_size)
{
    const float* x     = (const float*)d_in[0];
    const float* w_q   = (const float*)d_in[1];
    const float* w_k   = (const float*)d_in[2];
    const float* w_v   = (const float*)d_in[3];
    const float* w_o   = (const float*)d_in[4];
    const float* gamma = (const float*)d_in[5];
    const float* beta  = (const float*)d_in[6];
    float* out = (float*)d_out;

    // scratch pointers (module globals; no allocation)
    float *q_p, *k_p, *v_p, *ctx_p, *attn_scr;
    cudaGetSymbolAddress((void**)&q_p,      g_q);
    cudaGetSymbolAddress((void**)&k_p,      g_k);
    cudaGetSymbolAddress((void**)&v_p,      g_v);
    cudaGetSymbolAddress((void**)&ctx_p,    g_ctx);
    cudaGetSymbolAddress((void**)&attn_scr, g_attn_scratch);

    // If the harness expects the (out, attn) tuple flattened, attn lives
    // right after out in d_out; otherwise keep it in scratch.
    float* attn = ((size_t)out_size >= OUT_ELEMS + ATTN_ELEMS)
                      ? out + OUT_ELEMS : attn_scr;

    const int M = Bq * Sq;   // 8192
    const int N = DMq;       // 1024
    const int K = DMq;       // 1024

    dim3 gemm_grid(N / 128, M / 128);   // (8, 64)

    // 1) Q/K/V projections
    gemm_xw_kernel<false><<<gemm_grid, 256>>>(x, w_q, nullptr, q_p, M, N, K);
    gemm_xw_kernel<false><<<gemm_grid, 256>>>(x, w_k, nullptr, k_p, M, N, K);
    gemm_xw_kernel<false><<<gemm_grid, 256>>>(x, w_v, nullptr, v_p, M, N, K);

    // 2) scores (scaled)
    dim3 sc_grid(Sq / 128, Sq / 128, Bq * Hq);  // (16,16,64)
    scores_kernel<<<sc_grid, 256>>>(q_p, k_p, attn);

    // 3) softmax rows
    softmax_kernel<<<Bq * Hq * Sq, 256>>>(attn);

    // 4) ctx = attn @ V
    dim3 cx_grid(Sq / 128, Bq * Hq);            // (16,64)
    ctx_kernel<<<cx_grid, 256>>>(attn, v_p, ctx_p);

    // 5) out = ctx @ w_o + x   (pre-LN, into d_out)
    gemm_xw_kernel<true><<<gemm_grid, 256>>>(ctx_p, w_o, x, out, M, N, K);

    // 6) LayerNorm in place
    ln_kernel<<<M, 256>>>(out, gamma, beta);
}

// round 4
// speedup vs baseline: 1.4341x; 1.4341x over previous
#include <cuda_runtime.h>
#include <math.h>
#include <stddef.h>

// Problem constants
#define Bq   4
#define Sq   2048
#define Hq   16
#define DKq  64
#define DMq  1024
#define OUT_ELEMS   ((size_t)Bq * Sq * DMq)                 // 8,388,608
#define ATTN_ELEMS  ((size_t)Bq * Hq * (size_t)Sq * Sq)     // 268,435,456

// ---------------- scratch (allocation-free: __device__ globals) ----------------
__device__ float g_q  [Bq * Sq * DMq];
__device__ float g_k  [Bq * Sq * DMq];
__device__ float g_v  [Bq * Sq * DMq];
__device__ float g_ctx[Bq * Sq * DMq];
__device__ float g_attn_scratch[ATTN_ELEMS];   // fallback if harness wants only `out`

// ---------------- tf32 mma helpers ----------------
__device__ __forceinline__ unsigned f2tf(float x) {
    unsigned u;
    asm("cvt.rna.tf32.f32 %0, %1;" : "=r"(u) : "f"(x));
    return u;
}

// D += A(16x8 row) * B(8x8 col) ; tf32 inputs, fp32 accum
__device__ __forceinline__ void mma8(float c[4], const unsigned a[4], const unsigned b[2]) {
    asm volatile(
        "mma.sync.aligned.m16n8k8.row.col.f32.tf32.tf32.f32 "
        "{%0,%1,%2,%3}, {%4,%5,%6,%7}, {%8,%9}, {%0,%1,%2,%3};"
        : "+f"(c[0]), "+f"(c[1]), "+f"(c[2]), "+f"(c[3])
        : "r"(a[0]), "r"(a[1]), "r"(a[2]), "r"(a[3]), "r"(b[0]), "r"(b[1]));
}

// =====================================================================
// Proj GEMM (tensor cores): C[M,N] = A[M,K] * W[K,N] (+res)
// BM=128, BN=256, BK=16, 256 threads = 8 warps (2m x 4n), warp tile 64x64.
// As stored [k][m] (stride 136), Ws stored [k][n] (stride 264) — both give
// conflict-free fragment reads (stride % 32 == 8).
// =====================================================================
template<bool RES>
__global__ __launch_bounds__(256)
void gemm_mma(const float* __restrict__ A, const float* __restrict__ W,
              const float* __restrict__ res, float* __restrict__ C,
              int M, int N, int K)
{
    __shared__ unsigned As[16][136];
    __shared__ unsigned Ws[16][264];

    const int tid  = threadIdx.x;
    const int wid  = tid >> 5;
    const int lane = tid & 31;
    const int g    = lane >> 2;     // groupID 0..7
    const int tg   = lane & 3;      // thread-in-group 0..3
    const int wm   = (wid >> 2) * 64;
    const int wn   = (wid & 3) * 64;
    const int bm   = blockIdx.y * 128;
    const int bn   = blockIdx.x * 256;

    float acc[4][8][4];
    #pragma unroll
    for (int im = 0; im < 4; im++)
        #pragma unroll
        for (int in = 0; in < 8; in++)
            #pragma unroll
            for (int r = 0; r < 4; r++) acc[im][in][r] = 0.f;

    for (int k0 = 0; k0 < K; k0 += 16) {
        // A tile 128x16 -> As[k][m] (transposed store, tf32 convert)
        #pragma unroll
        for (int i = 0; i < 2; i++) {
            int idx = tid + i * 256;          // float4 index, 4 per row
            int row = idx >> 2;
            int c4  = (idx & 3) * 4;
            float4 v = *reinterpret_cast<const float4*>(&A[(size_t)(bm + row) * K + k0 + c4]);
            As[c4 + 0][row] = f2tf(v.x);
            As[c4 + 1][row] = f2tf(v.y);
            As[c4 + 2][row] = f2tf(v.z);
            As[c4 + 3][row] = f2tf(v.w);
        }
        // W tile 16x256 -> Ws[k][n] (natural layout, vectorized store)
        #pragma unroll
        for (int i = 0; i < 4; i++) {
            int idx = tid + i * 256;          // float4 index, 64 per row
            int kk  = idx >> 6;
            int n4  = (idx & 63) * 4;
            float4 v = *reinterpret_cast<const float4*>(&W[(size_t)(k0 + kk) * N + bn + n4]);
            uint4 u = make_uint4(f2tf(v.x), f2tf(v.y), f2tf(v.z), f2tf(v.w));
            *reinterpret_cast<uint4*>(&Ws[kk][n4]) = u;
        }
        __syncthreads();

        #pragma unroll
        for (int ks = 0; ks < 2; ks++) {
            const int kb = ks * 8;
            unsigned af[4][4], bf[8][2];
            #pragma unroll
            for (int im = 0; im < 4; im++) {
                int r = wm + im * 16 + g;
                af[im][0] = As[kb + tg    ][r];
                af[im][1] = As[kb + tg    ][r + 8];
                af[im][2] = As[kb + tg + 4][r];
                af[im][3] = As[kb + tg + 4][r + 8];
            }
            #pragma unroll
            for (int in = 0; in < 8; in++) {
                int n = wn + in * 8 + g;
                bf[in][0] = Ws[kb + tg    ][n];
                bf[in][1] = Ws[kb + tg + 4][n];
            }
            #pragma unroll
            for (int im = 0; im < 4; im++)
                #pragma unroll
                for (int in = 0; in < 8; in++)
                    mma8(acc[im][in], af[im], bf[in]);
        }
        __syncthreads();
    }

    // epilogue
    #pragma unroll
    for (int im = 0; im < 4; im++) {
        #pragma unroll
        for (int in = 0; in < 8; in++) {
            int r0 = bm + wm + im * 16 + g;
            int c  = bn + wn + in * 8 + 2 * tg;
            float2 v0 = make_float2(acc[im][in][0], acc[im][in][1]);
            float2 v1 = make_float2(acc[im][in][2], acc[im][in][3]);
            if (RES) {
                float2 r0v = *reinterpret_cast<const float2*>(&res[(size_t)r0 * N + c]);
                float2 r1v = *reinterpret_cast<const float2*>(&res[(size_t)(r0 + 8) * N + c]);
                v0.x += r0v.x; v0.y += r0v.y;
                v1.x += r1v.x; v1.y += r1v.y;
            }
            *reinterpret_cast<float2*>(&C[(size_t)r0 * N + c])       = v0;
            *reinterpret_cast<float2*>(&C[(size_t)(r0 + 8) * N + c]) = v1;
        }
    }
}

// =====================================================================
// Scores (tensor cores): attn[bh,q,k] = (Q/8) . K  over d=64
// BM=128 (q), BN=256 (k-seq), full K=64 loaded once.
// 256 threads = 8 warps (2m x 4n), warp tile 64x64. Dynamic smem 100KB.
// =====================================================================
#define SCORES_SMEM ((64 * 136 + 64 * 264) * 4)

__global__ __launch_bounds__(256)
void scores_mma(const float* __restrict__ Q, const float* __restrict__ Kv,
                float* __restrict__ attn)
{
    extern __shared__ unsigned sm[];
    unsigned (*Qs)[136] = reinterpret_cast<unsigned(*)[136]>(sm);            // [64][136]  A:[k][m]
    unsigned (*Ks)[264] = reinterpret_cast<unsigned(*)[264]>(sm + 64 * 136); // [64][264]  B:[k][n]

    const int bh = blockIdx.z;
    const int b  = bh >> 4;
    const int h  = bh & 15;
    const float* qb = Q  + (size_t)b * Sq * DMq + h * DKq;
    const float* kb = Kv + (size_t)b * Sq * DMq + h * DKq;
    const int q0 = blockIdx.y * 128;
    const int n0 = blockIdx.x * 256;

    const int tid  = threadIdx.x;
    const int wid  = tid >> 5;
    const int lane = tid & 31;
    const int g    = lane >> 2;
    const int tg   = lane & 3;
    const int wm   = (wid >> 2) * 64;
    const int wn   = (wid & 3) * 64;

    // Q tile: 128 rows x 64 (16 float4/row), scaled by 1/8, transposed to Qs[k][m]
    #pragma unroll
    for (int i = 0; i < 8; i++) {
        int idx = tid + i * 256;
        int row = idx >> 4;
        int c4  = (idx & 15) * 4;
        float4 v = *reinterpret_cast<const float4*>(&qb[(size_t)(q0 + row) * DMq + c4]);
        Qs[c4 + 0][row] = f2tf(v.x * 0.125f);
        Qs[c4 + 1][row] = f2tf(v.y * 0.125f);
        Qs[c4 + 2][row] = f2tf(v.z * 0.125f);
        Qs[c4 + 3][row] = f2tf(v.w * 0.125f);
    }
    // K tile: 256 rows x 64, transposed to Ks[k][n]
    #pragma unroll
    for (int i = 0; i < 16; i++) {
        int idx = tid + i * 256;
        int row = idx >> 4;
        int c4  = (idx & 15) * 4;
        float4 v = *reinterpret_cast<const float4*>(&kb[(size_t)(n0 + row) * DMq + c4]);
        Ks[c4 + 0][row] = f2tf(v.x);
        Ks[c4 + 1][row] = f2tf(v.y);
        Ks[c4 + 2][row] = f2tf(v.z);
        Ks[c4 + 3][row] = f2tf(v.w);
    }
    __syncthreads();

    float acc[4][8][4];
    #pragma unroll
    for (int im = 0; im < 4; im++)
        #pragma unroll
        for (int in = 0; in < 8; in++)
            #pragma unroll
            for (int r = 0; r < 4; r++) acc[im][in][r] = 0.f;

    #pragma unroll
    for (int ks = 0; ks < 8; ks++) {
        const int kb8 = ks * 8;
        unsigned af[4][4], bf[8][2];
        #pragma unroll
        for (int im = 0; im < 4; im++) {
            int r = wm + im * 16 + g;
            af[im][0] = Qs[kb8 + tg    ][r];
            af[im][1] = Qs[kb8 + tg    ][r + 8];
            af[im][2] = Qs[kb8 + tg + 4][r];
            af[im][3] = Qs[kb8 + tg + 4][r + 8];
        }
        #pragma unroll
        for (int in = 0; in < 8; in++) {
            int n = wn + in * 8 + g;
            bf[in][0] = Ks[kb8 + tg    ][n];
            bf[in][1] = Ks[kb8 + tg + 4][n];
        }
        #pragma unroll
        for (int im = 0; im < 4; im++)
            #pragma unroll
            for (int in = 0; in < 8; in++)
                mma8(acc[im][in], af[im], bf[in]);
    }

    const size_t base = (size_t)bh * Sq * Sq;
    #pragma unroll
    for (int im = 0; im < 4; im++) {
        #pragma unroll
        for (int in = 0; in < 8; in++) {
            int r0 = q0 + wm + im * 16 + g;
            int c  = n0 + wn + in * 8 + 2 * tg;
            *reinterpret_cast<float2*>(&attn[base + (size_t)r0 * Sq + c]) =
                make_float2(acc[im][in][0], acc[im][in][1]);
            *reinterpret_cast<float2*>(&attn[base + (size_t)(r0 + 8) * Sq + c]) =
                make_float2(acc[im][in][2], acc[im][in][3]);
        }
    }
}

// =====================================================================
// Row softmax in place (float4): 131072 rows of 2048, 256 thr/row.
// =====================================================================
__global__ __launch_bounds__(256)
void softmax_kernel(float* __restrict__ attn)
{
    __shared__ float red[256];
    float4* p = reinterpret_cast<float4*>(attn + (size_t)blockIdx.x * Sq);
    const int tid = threadIdx.x;

    float4 a = p[tid];
    float4 b = p[tid + 256];
    float mx = fmaxf(fmaxf(fmaxf(a.x, a.y), fmaxf(a.z, a.w)),
                     fmaxf(fmaxf(b.x, b.y), fmaxf(b.z, b.w)));
    red[tid] = mx;
    __syncthreads();
    #pragma unroll
    for (int s = 128; s > 0; s >>= 1) {
        if (tid < s) red[tid] = fmaxf(red[tid], red[tid + s]);
        __syncthreads();
    }
    mx = red[0];
    __syncthreads();

    a.x = __expf(a.x - mx); a.y = __expf(a.y - mx);
    a.z = __expf(a.z - mx); a.w = __expf(a.w - mx);
    b.x = __expf(b.x - mx); b.y = __expf(b.y - mx);
    b.z = __expf(b.z - mx); b.w = __expf(b.w - mx);
    float sum = a.x + a.y + a.z + a.w + b.x + b.y + b.z + b.w;
    red[tid] = sum;
    __syncthreads();
    #pragma unroll
    for (int s = 128; s > 0; s >>= 1) {
        if (tid < s) red[tid] += red[tid + s];
        __syncthreads();
    }
    const float inv = 1.f / red[0];
    a.x *= inv; a.y *= inv; a.z *= inv; a.w *= inv;
    b.x *= inv; b.y *= inv; b.z *= inv; b.w *= inv;
    p[tid]       = a;
    p[tid + 256] = b;
}

// =====================================================================
// ctx (tensor cores): ctx[b,s,h,:] = attn[bh,s,:] @ V[b,:,h,:]
// BM=256, BN=64, BK=32; 128 threads = 4 warps (m), warp tile 64x64.
// As [k][m] stride 264, Vs [k][n] stride 72.
// =====================================================================
__global__ __launch_bounds__(128)
void ctx_mma(const float* __restrict__ attn, const float* __restrict__ V,
             float* __restrict__ ctx)
{
    __shared__ unsigned As[32][264];
    __shared__ unsigned Vs[32][72];

    const int bh = blockIdx.y;
    const int b  = bh >> 4;
    const int h  = bh & 15;
    const float* ab = attn + (size_t)bh * Sq * Sq;
    const float* vb = V    + (size_t)b * Sq * DMq + h * DKq;
    const int m0 = blockIdx.x * 256;

    const int tid  = threadIdx.x;
    const int wid  = tid >> 5;
    const int lane = tid & 31;
    const int g    = lane >> 2;
    const int tg   = lane & 3;
    const int wm   = wid * 64;

    float acc[4][8][4];
    #pragma unroll
    for (int im = 0; im < 4; im++)
        #pragma unroll
        for (int in = 0; in < 8; in++)
            #pragma unroll
            for (int r = 0; r < 4; r++) acc[im][in][r] = 0.f;

    for (int k0 = 0; k0 < Sq; k0 += 32) {
        // attn tile 256x32 (8 float4/row) -> As[k][m] transposed
        #pragma unroll
        for (int i = 0; i < 16; i++) {
            int idx = tid + i * 128;
            int row = idx >> 3;
            int c4  = (idx & 7) * 4;
            float4 v = *reinterpret_cast<const float4*>(&ab[(size_t)(m0 + row) * Sq + k0 + c4]);
            As[c4 + 0][row] = f2tf(v.x);
            As[c4 + 1][row] = f2tf(v.y);
            As[c4 + 2][row] = f2tf(v.z);
            As[c4 + 3][row] = f2tf(v.w);
        }
        // V tile 32x64 (16 float4/row) -> Vs[k][n] natural
        #pragma unroll
        for (int i = 0; i < 4; i++) {
            int idx = tid + i * 128;
            int kk  = idx >> 4;
            int n4  = (idx & 15) * 4;
            float4 v = *reinterpret_cast<const float4*>(&vb[(size_t)(k0 + kk) * DMq + n4]);
            uint4 u = make_uint4(f2tf(v.x), f2tf(v.y), f2tf(v.z), f2tf(v.w));
            *reinterpret_cast<uint4*>(&Vs[kk][n4]) = u;
        }
        __syncthreads();

        #pragma unroll
        for (int ks = 0; ks < 4; ks++) {
            const int kb8 = ks * 8;
            unsigned af[4][4], bf[8][2];
            #pragma unroll
            for (int im = 0; im < 4; im++) {
                int r = wm + im * 16 + g;
                af[im][0] = As[kb8 + tg    ][r];
                af[im][1] = As[kb8 + tg    ][r + 8];
                af[im][2] = As[kb8 + tg + 4][r];
                af[im][3] = As[kb8 + tg + 4][r + 8];
            }
            #pragma unroll
            for (int in = 0; in < 8; in++) {
                int n = in * 8 + g;
                bf[in][0] = Vs[kb8 + tg    ][n];
                bf[in][1] = Vs[kb8 + tg + 4][n];
            }
            #pragma unroll
            for (int im = 0; im < 4; im++)
                #pragma unroll
                for (int in = 0; in < 8; in++)
                    mma8(acc[im][in], af[im], bf[in]);
        }
        __syncthreads();
    }

    #pragma unroll
    for (int im = 0; im < 4; im++) {
        #pragma unroll
        for (int in = 0; in < 8; in++) {
            int s0 = m0 + wm + im * 16 + g;
            int c  = h * DKq + in * 8 + 2 * tg;
            *reinterpret_cast<float2*>(&ctx[(size_t)(b * Sq + s0) * DMq + c]) =
                make_float2(acc[im][in][0], acc[im][in][1]);
            *reinterpret_cast<float2*>(&ctx[(size_t)(b * Sq + s0 + 8) * DMq + c]) =
                make_float2(acc[im][in][2], acc[im][in][3]);
        }
    }
}

// =====================================================================
// LayerNorm in place: 8192 rows of 1024, 256 thr/row.
// =====================================================================
__global__ __launch_bounds__(256)
void ln_kernel(float* __restrict__ out, const float* __restrict__ gamma,
               const float* __restrict__ beta)
{
    __shared__ float red[256];
    float* p = out + (size_t)blockIdx.x * DMq;
    const int tid = threadIdx.x;

    float v[4];
    float s = 0.f;
    #pragma unroll
    for (int i = 0; i < 4; i++) {
        v[i] = p[tid + i * 256];
        s += v[i];
    }
    red[tid] = s;
    __syncthreads();
    #pragma unroll
    for (int st = 128; st > 0; st >>= 1) {
        if (tid < st) red[tid] += red[tid + st];
        __syncthreads();
    }
    const float mu = red[0] * (1.f / DMq);
    __syncthreads();

    float s2 = 0.f;
    #pragma unroll
    for (int i = 0; i < 4; i++) {
        float d = v[i] - mu;
        s2 += d * d;
    }
    red[tid] = s2;
    __syncthreads();
    #pragma unroll
    for (int st = 128; st > 0; st >>= 1) {
        if (tid < st) red[tid] += red[tid + st];
        __syncthreads();
    }
    const float inv = rsqrtf(red[0] * (1.f / DMq) + 1e-6f);
    #pragma unroll
    for (int i = 0; i < 4; i++) {
        int c = tid + i * 256;
        p[c] = (v[i] - mu) * inv * gamma[c] + beta[c];
    }
}

// =====================================================================
extern "C" void kernel_launch(void* const* d_in, const int* in_sizes, int n_in,
                              void* d_out, int out_size)
{
    const float* x     = (const float*)d_in[0];
    const float* w_q   = (const float*)d_in[1];
    const float* w_k   = (const float*)d_in[2];
    const float* w_v   = (const float*)d_in[3];
    const float* w_o   = (const float*)d_in[4];
    const float* gamma = (const float*)d_in[5];
    const float* beta  = (const float*)d_in[6];
    float* out = (float*)d_out;

    float *q_p, *k_p, *v_p, *ctx_p, *attn_scr;
    cudaGetSymbolAddress((void**)&q_p,      g_q);
    cudaGetSymbolAddress((void**)&k_p,      g_k);
    cudaGetSymbolAddress((void**)&v_p,      g_v);
    cudaGetSymbolAddress((void**)&ctx_p,    g_ctx);
    cudaGetSymbolAddress((void**)&attn_scr, g_attn_scratch);

    float* attn = ((size_t)out_size >= OUT_ELEMS + ATTN_ELEMS)
                      ? out + OUT_ELEMS : attn_scr;

    const int M = Bq * Sq;   // 8192
    const int N = DMq;       // 1024
    const int K = DMq;       // 1024

    // allow 100KB dynamic smem for scores (idempotent)
    cudaFuncSetAttribute(scores_mma, cudaFuncAttributeMaxDynamicSharedMemorySize, SCORES_SMEM);

    dim3 gemm_grid(N / 256, M / 128);            // (4, 64)

    // 1) Q/K/V projections (tensor cores)
    gemm_mma<false><<<gemm_grid, 256>>>(x, w_q, nullptr, q_p, M, N, K);
    gemm_mma<false><<<gemm_grid, 256>>>(x, w_k, nullptr, k_p, M, N, K);
    gemm_mma<false><<<gemm_grid, 256>>>(x, w_v, nullptr, v_p, M, N, K);

    // 2) scores (scaled, tensor cores)
    dim3 sc_grid(Sq / 256, Sq / 128, Bq * Hq);   // (8, 16, 64)
    scores_mma<<<sc_grid, 256, SCORES_SMEM>>>(q_p, k_p, attn);

    // 3) softmax rows
    softmax_kernel<<<Bq * Hq * Sq, 256>>>(attn);

    // 4) ctx = attn @ V (tensor cores)
    dim3 cx_grid(Sq / 256, Bq * Hq);             // (8, 64)
    ctx_mma<<<cx_grid, 128>>>(attn, v_p, ctx_p);

    // 5) out = ctx @ w_o + x (tensor cores)
    gemm_mma<true><<<gemm_grid, 256>>>(ctx_p, w_o, x, out, M, N, K);

    // 6) LayerNorm in place
    ln_kernel<<<M, 256>>>(out, gamma, beta);
}